// round 1
// baseline (speedup 1.0000x reference)
#include <cuda_runtime.h>
#include <cstdint>
#include <math.h>

#define BATCH   256
#define SEQL    512
#define INDIM   64
#define UNITS   256
#define OUTSTEPS 64
#define OUTDIMS 32
#define G4      1024   // 4 * UNITS

// ---------------- scratch (static device globals; no allocation) ----------------
__device__ float d_X[BATCH * SEQL * UNITS];            // conv output          134 MB
__device__ float d_ZX[(size_t)SEQL * BATCH * G4];      // x@W + b, [t][b][1024] 537 MB
__device__ float d_HSEQ[BATCH * SEQL * UNITS];         // encoder hidden seq   134 MB
__device__ float d_FSEQ[BATCH * OUTSTEPS * UNITS];     // decoder hidden seq    17 MB
__device__ float d_Hbuf[2][BATCH * UNITS];
__device__ float d_Cbuf[2][BATCH * UNITS];
__device__ float d_WSUM[UNITS * G4];                   // cell_W + cell_U

// ---------------- conv1d 'same' (K=5) + bias + relu ----------------
// grid (L/32, B), 256 threads (one per output unit), 32 output positions per block
__global__ __launch_bounds__(256) void conv_relu_kernel(
    const float* __restrict__ in, const float* __restrict__ ck, const float* __restrict__ cb)
{
    __shared__ __align__(16) float ins[36][INDIM];   // rows l0-2 .. l0+33
    int tid = threadIdx.x;
    int l0 = blockIdx.x * 32;
    int b  = blockIdx.y;
    #pragma unroll
    for (int i = 0; i < 9; i++) {
        int flat = tid + 256 * i;
        if (flat < 36 * 64) {
            int r = flat >> 6, c = flat & 63;
            int l = l0 - 2 + r;
            ins[r][c] = (l >= 0 && l < SEQL) ? in[((size_t)b * SEQL + l) * INDIM + c] : 0.f;
        }
    }
    __syncthreads();
    int u = tid;
    float bias = cb[u];
    float acc[32];
    #pragma unroll
    for (int l = 0; l < 32; l++) acc[l] = bias;
    for (int i = 0; i < 64; i++) {
        float v[36];
        #pragma unroll
        for (int r = 0; r < 36; r++) v[r] = ins[r][i];
        #pragma unroll
        for (int w = 0; w < 5; w++) {
            float kw = ck[(w * 64 + i) * 256 + u];
            #pragma unroll
            for (int l = 0; l < 32; l++) acc[l] += v[l + w] * kw;
        }
    }
    #pragma unroll
    for (int l = 0; l < 32; l++)
        d_X[((size_t)b * SEQL + l0 + l) * UNITS + u] = fmaxf(acc[l], 0.f);
}

// ---------------- ZX = X @ enc_W + enc_b   (M=131072, N=1024, K=256) ----------------
// 128x128 tile, 8x8 micro, k-chunk 8. Output remapped to [t][b][1024].
__global__ __launch_bounds__(256) void gemm_zx_kernel(
    const float* __restrict__ W, const float* __restrict__ bias)
{
    __shared__ __align__(16) float As[8][128];
    __shared__ __align__(16) float Bs[8][128];
    int tid = threadIdx.x;
    int n0 = blockIdx.x * 128;
    int m0 = blockIdx.y * 128;
    float acc[8][8];
    #pragma unroll
    for (int i = 0; i < 8; i++)
        #pragma unroll
        for (int j = 0; j < 8; j++) acc[i][j] = 0.f;
    int tx = tid & 15, ty = tid >> 4;
    int am = tid >> 1, ak = (tid & 1) * 4;
    int bk = tid >> 5, bn = (tid & 31) * 4;
    for (int k0 = 0; k0 < 256; k0 += 8) {
        float4 av = *(const float4*)&d_X[(size_t)(m0 + am) * 256 + k0 + ak];
        float4 bv = *(const float4*)&W[(size_t)(k0 + bk) * G4 + n0 + bn];
        As[ak + 0][am] = av.x; As[ak + 1][am] = av.y;
        As[ak + 2][am] = av.z; As[ak + 3][am] = av.w;
        *(float4*)&Bs[bk][bn] = bv;
        __syncthreads();
        #pragma unroll
        for (int k = 0; k < 8; k++) {
            float a[8], bb[8];
            *(float4*)&a[0] = *(const float4*)&As[k][ty * 8];
            *(float4*)&a[4] = *(const float4*)&As[k][ty * 8 + 4];
            *(float4*)&bb[0] = *(const float4*)&Bs[k][tx * 8];
            *(float4*)&bb[4] = *(const float4*)&Bs[k][tx * 8 + 4];
            #pragma unroll
            for (int i = 0; i < 8; i++)
                #pragma unroll
                for (int j = 0; j < 8; j++) acc[i][j] += a[i] * bb[j];
        }
        __syncthreads();
    }
    #pragma unroll
    for (int i = 0; i < 8; i++) {
        int m = m0 + ty * 8 + i;
        int bIdx = m >> 9;       // m / 512  -> batch
        int t    = m & 511;      // m % 512  -> time
        float* crow = d_ZX + ((size_t)t * BATCH + bIdx) * G4 + n0 + tx * 8;
        #pragma unroll
        for (int j = 0; j < 8; j++) crow[j] = acc[i][j] + bias[n0 + tx * 8 + j];
    }
}

// ---------------- init & weight-combine ----------------
__global__ void zero_hc_kernel() {
    int i = blockIdx.x * 256 + threadIdx.x;
    d_Hbuf[0][i] = 0.f;
    d_Cbuf[0][i] = 0.f;
}
__global__ void wsum_kernel(const float* __restrict__ W, const float* __restrict__ Uc) {
    int i = blockIdx.x * 256 + threadIdx.x;
    d_WSUM[i] = W[i] + Uc[i];
}

// ---------------- one LSTM step:  z = (zx or bias) + h @ U ; gates; update ----------------
// grid (UNITS/64 = 4, BATCH/16 = 16), 256 threads.
// Thread computes all 4 gates for 4 batch rows of one unit (16 accumulators).
__global__ __launch_bounds__(256) void lstm_step_kernel(
    int hin, int hout, int t, int is_dec,
    const float* __restrict__ Uenc, const float* __restrict__ cell_bias)
{
    __shared__ __align__(16) float hT[UNITS][16];   // [k][b_local]
    __shared__ __align__(16) float Us[16][256];     // [k][uu*4 + gate]

    const float* Hin  = d_Hbuf[hin];
    const float* Cin  = d_Cbuf[hin];
    float*       Hout = d_Hbuf[hout];
    float*       Cout = d_Cbuf[hout];
    const float* U    = is_dec ? d_WSUM : Uenc;
    const float* zx   = is_dec ? nullptr : (d_ZX + (size_t)t * BATCH * G4);
    float*       seq  = is_dec ? d_FSEQ : d_HSEQ;
    int seq_stride    = is_dec ? OUTSTEPS : SEQL;

    int tid = threadIdx.x;
    int u0 = blockIdx.x * 64;
    int b0 = blockIdx.y * 16;

    // load h tile transposed into smem
    #pragma unroll
    for (int i = 0; i < 16; i++) {
        int flat = tid + 256 * i;       // 4096 = 16 b x 256 k
        int bl = flat >> 8;
        int k  = flat & 255;
        hT[k][bl] = Hin[(b0 + bl) * UNITS + k];
    }

    int tb = tid >> 6;      // 0..3 -> batch group
    int tu = tid & 63;      // 0..63 -> unit within tile
    int u  = u0 + tu;

    float acc[4][4];        // [b][gate: i,f,g,o]
    #pragma unroll
    for (int bb = 0; bb < 4; bb++) {
        int b = b0 + tb * 4 + bb;
        #pragma unroll
        for (int g = 0; g < 4; g++)
            acc[bb][g] = is_dec ? cell_bias[g * 256 + u]
                                : zx[(size_t)b * G4 + g * 256 + u];
    }

    for (int kc = 0; kc < 256; kc += 16) {
        __syncthreads();    // hT ready on first pass; protects Us reuse after
        #pragma unroll
        for (int i = 0; i < 16; i++) {
            int flat = tid + 256 * i;   // 16 k x 256 cols
            int k = flat >> 8;
            int j = flat & 255;
            int g = j >> 6, uu = j & 63;
            Us[k][uu * 4 + g] = U[(size_t)(kc + k) * G4 + g * 256 + u0 + uu];
        }
        __syncthreads();
        #pragma unroll
        for (int k = 0; k < 16; k++) {
            float4 hv = *(const float4*)&hT[kc + k][tb * 4];
            float4 uv = *(const float4*)&Us[k][tu * 4];
            acc[0][0] += hv.x * uv.x; acc[0][1] += hv.x * uv.y;
            acc[0][2] += hv.x * uv.z; acc[0][3] += hv.x * uv.w;
            acc[1][0] += hv.y * uv.x; acc[1][1] += hv.y * uv.y;
            acc[1][2] += hv.y * uv.z; acc[1][3] += hv.y * uv.w;
            acc[2][0] += hv.z * uv.x; acc[2][1] += hv.z * uv.y;
            acc[2][2] += hv.z * uv.z; acc[2][3] += hv.z * uv.w;
            acc[3][0] += hv.w * uv.x; acc[3][1] += hv.w * uv.y;
            acc[3][2] += hv.w * uv.z; acc[3][3] += hv.w * uv.w;
        }
    }

    // gates + state update (Keras order i, f, g, o)
    #pragma unroll
    for (int bb = 0; bb < 4; bb++) {
        int b = b0 + tb * 4 + bb;
        float zi = acc[bb][0], zf = acc[bb][1], zg = acc[bb][2], zo = acc[bb][3];
        float co = Cin[b * UNITS + u];
        float ig = 1.f / (1.f + expf(-zi));
        float fg = 1.f / (1.f + expf(-zf));
        float gg = tanhf(zg);
        float og = 1.f / (1.f + expf(-zo));
        float cn = fg * co + ig * gg;
        float hn = og * tanhf(cn);
        Cout[b * UNITS + u] = cn;
        Hout[b * UNITS + u] = hn;
        seq[((size_t)b * seq_stride + t) * UNITS + u] = hn;
    }
}

// ---------------- backcast = HSEQ @ back_W + back_b  (M=131072, N=64, K=256) ----------------
__global__ __launch_bounds__(256) void gemm_back_kernel(
    const float* __restrict__ Bw, const float* __restrict__ bias, float* __restrict__ out)
{
    __shared__ __align__(16) float As[16][64];
    __shared__ __align__(16) float Bs[16][64];
    int tid = threadIdx.x;
    int m0 = blockIdx.x * 64;
    int tx = tid & 15, ty = tid >> 4;
    float acc[4][4];
    #pragma unroll
    for (int i = 0; i < 4; i++)
        #pragma unroll
        for (int j = 0; j < 4; j++) acc[i][j] = 0.f;
    int lam = tid >> 2, lak = (tid & 3) * 4;
    int lbk = tid >> 4, lbn = (tid & 15) * 4;
    for (int k0 = 0; k0 < 256; k0 += 16) {
        float4 av = *(const float4*)&d_HSEQ[(size_t)(m0 + lam) * 256 + k0 + lak];
        float4 bv = *(const float4*)&Bw[(size_t)(k0 + lbk) * 64 + lbn];
        As[lak + 0][lam] = av.x; As[lak + 1][lam] = av.y;
        As[lak + 2][lam] = av.z; As[lak + 3][lam] = av.w;
        *(float4*)&Bs[lbk][lbn] = bv;
        __syncthreads();
        #pragma unroll
        for (int k = 0; k < 16; k++) {
            float a[4], bb4[4];
            *(float4*)&a[0]   = *(const float4*)&As[k][ty * 4];
            *(float4*)&bb4[0] = *(const float4*)&Bs[k][tx * 4];
            #pragma unroll
            for (int i = 0; i < 4; i++)
                #pragma unroll
                for (int j = 0; j < 4; j++) acc[i][j] += a[i] * bb4[j];
        }
        __syncthreads();
    }
    #pragma unroll
    for (int i = 0; i < 4; i++) {
        int m = m0 + ty * 4 + i;
        #pragma unroll
        for (int j = 0; j < 4; j++) {
            int n = tx * 4 + j;
            out[(size_t)m * 64 + n] = acc[i][j] + bias[n];
        }
    }
}

// ---------------- forecast = FSEQ @ fore_W + fore_b  (M=16384, N=32, K=256) ----------------
__global__ __launch_bounds__(256) void forecast_kernel(
    const float* __restrict__ Wf, const float* __restrict__ bf, float* __restrict__ out)
{
    __shared__ __align__(16) float rows[8][256];
    int tid = threadIdx.x;
    int m0 = blockIdx.x * 8;
    #pragma unroll
    for (int i = 0; i < 8; i++) {
        int flat = tid + 256 * i;
        int r = flat >> 8, c = flat & 255;
        rows[r][c] = d_FSEQ[(size_t)(m0 + r) * 256 + c];
    }
    __syncthreads();
    int r = tid >> 5, n = tid & 31;
    float acc = bf[n];
    #pragma unroll 8
    for (int k = 0; k < 256; k++) acc += rows[r][k] * Wf[k * 32 + n];
    out[(size_t)(m0 + r) * 32 + n] = acc;
}

// ---------------- launch ----------------
extern "C" void kernel_launch(void* const* d_in, const int* in_sizes, int n_in,
                              void* d_out, int out_size)
{
    const float* inputs = (const float*)d_in[0];
    const float* conv_k = (const float*)d_in[1];
    const float* conv_b = (const float*)d_in[2];
    const float* enc_W  = (const float*)d_in[3];
    const float* enc_U  = (const float*)d_in[4];
    const float* enc_b  = (const float*)d_in[5];
    const float* cell_W = (const float*)d_in[6];
    const float* cell_U = (const float*)d_in[7];
    const float* cell_b = (const float*)d_in[8];
    const float* fore_W = (const float*)d_in[9];
    const float* fore_b = (const float*)d_in[10];
    const float* back_W = (const float*)d_in[11];
    const float* back_b = (const float*)d_in[12];
    float* out = (float*)d_out;

    // conv + relu -> d_X
    conv_relu_kernel<<<dim3(SEQL / 32, BATCH), 256>>>(inputs, conv_k, conv_b);
    // ZX = X @ enc_W + enc_b  (parallel, hoisted out of recurrence)
    gemm_zx_kernel<<<dim3(G4 / 128, (BATCH * SEQL) / 128), 256>>>(enc_W, enc_b);
    // h0 = c0 = 0 ; decoder weight fold (input == hidden)
    zero_hc_kernel<<<(BATCH * UNITS) / 256, 256>>>();
    wsum_kernel<<<(UNITS * G4) / 256, 256>>>(cell_W, cell_U);

    // encoder recurrence (512 steps)
    int ping = 0;
    for (int t = 0; t < SEQL; t++) {
        lstm_step_kernel<<<dim3(4, 16), 256>>>(ping, 1 - ping, t, 0, enc_U, nullptr);
        ping = 1 - ping;
    }
    // decoder recurrence (64 steps), z = h @ (cell_W + cell_U) + cell_b
    for (int t = 0; t < OUTSTEPS; t++) {
        lstm_step_kernel<<<dim3(4, 16), 256>>>(ping, 1 - ping, t, 1, nullptr, cell_b);
        ping = 1 - ping;
    }

    // heads: forecast first, then backcast (tuple flatten order)
    forecast_kernel<<<(BATCH * OUTSTEPS) / 8, 256>>>(fore_W, fore_b, out);
    gemm_back_kernel<<<(BATCH * SEQL) / 64, 256>>>(back_W, back_b,
                                                   out + (size_t)BATCH * OUTSTEPS * OUTDIMS);
}

// round 2
// speedup vs baseline: 1.0650x; 1.0650x over previous
#include <cuda_runtime.h>
#include <cstdint>
#include <math.h>

#define BATCH    256
#define SEQL     512
#define INDIM    64
#define UNITS    256
#define OUTSTEPS 64
#define OUTDIMS  32
#define G4       1024   // 4 * UNITS
#define NCTA_REC 128

typedef unsigned long long ull;

// ---------------- scratch (static device globals; no allocation) ----------------
__device__ float d_X[BATCH * SEQL * UNITS];            // conv output
__device__ float d_ZX[(size_t)SEQL * BATCH * G4];      // x@W + b, [t][b][1024]
__device__ float d_HSEQ[BATCH * SEQL * UNITS];         // encoder hidden seq
__device__ float d_FSEQ[BATCH * OUTSTEPS * UNITS];     // decoder hidden seq
__device__ float d_Hbuf[2][BATCH * UNITS];             // ping-pong h
__device__ unsigned g_cnt = 0;                          // grid barrier
__device__ unsigned g_gen = 0;

// ---------------- f32x2 helpers ----------------
__device__ __forceinline__ ull pk2(float lo, float hi) {
    ull r; asm("mov.b64 %0, {%1, %2};" : "=l"(r) : "f"(lo), "f"(hi)); return r;
}
__device__ __forceinline__ void upk2(ull v, float& lo, float& hi) {
    asm("mov.b64 {%0, %1}, %2;" : "=f"(lo), "=f"(hi) : "l"(v));
}
__device__ __forceinline__ void ffma2(ull& d, ull a, ull b) {
    asm("fma.rn.f32x2 %0, %1, %2, %0;" : "+l"(d) : "l"(a), "l"(b));
}

// ---------------- conv1d 'same' (K=5) + bias + relu, f32x2 over unit pairs ----------------
// grid (16, 256), 256 threads. thread = (lh 0/1 half of 32 l-positions, tu unit-pair)
__global__ __launch_bounds__(256) void conv_relu_kernel(
    const float* __restrict__ in, const float* __restrict__ ck, const float* __restrict__ cb)
{
    __shared__ __align__(16) ull ins2[36 * 64];   // input rows duplicated into both lanes
    int tid = threadIdx.x;
    int l0 = blockIdx.x * 32;
    int b  = blockIdx.y;
    for (int idx = tid; idx < 36 * 64; idx += 256) {
        int r = idx >> 6, ci = idx & 63;
        int l = l0 - 2 + r;
        float v = (l >= 0 && l < SEQL) ? in[((size_t)b * SEQL + l) * INDIM + ci] : 0.f;
        ins2[idx] = pk2(v, v);
    }
    __syncthreads();

    int tu = tid & 127;        // unit pair: units 2tu, 2tu+1 (lanes of f32x2)
    int lh = tid >> 7;         // which 16 of the 32 l positions
    int lbase = lh * 16;
    ull acc[16];
    ull binit = *(const ull*)&cb[2 * tu];
    #pragma unroll
    for (int j = 0; j < 16; j++) acc[j] = binit;

    for (int i = 0; i < 64; i++) {
        ull v2[20];
        #pragma unroll
        for (int r = 0; r < 20; r++) v2[r] = ins2[(lbase + r) * 64 + i];
        #pragma unroll
        for (int w = 0; w < 5; w++) {
            ull kw2 = *(const ull*)&ck[((size_t)(w * 64 + i)) * 256 + 2 * tu];
            #pragma unroll
            for (int j = 0; j < 16; j++) ffma2(acc[j], v2[j + w], kw2);
        }
    }
    #pragma unroll
    for (int j = 0; j < 16; j++) {
        float a, c2; upk2(acc[j], a, c2);
        float2 o = make_float2(fmaxf(a, 0.f), fmaxf(c2, 0.f));
        *(float2*)&d_X[((size_t)b * SEQL + l0 + lbase + j) * UNITS + 2 * tu] = o;
    }
}

// ---------------- ZX = X @ enc_W + enc_b (M=131072, N=1024, K=256), f32x2 ----------------
__global__ __launch_bounds__(256) void gemm_zx_kernel(
    const float* __restrict__ W, const float* __restrict__ bias)
{
    __shared__ __align__(16) ull   As2[8 * 128];   // A rows duplicated into both lanes
    __shared__ __align__(16) float Bs [8 * 128];
    int tid = threadIdx.x;
    int n0 = blockIdx.x * 128;
    int m0 = blockIdx.y * 128;
    ull acc[8][4];
    #pragma unroll
    for (int i = 0; i < 8; i++)
        #pragma unroll
        for (int j = 0; j < 4; j++) acc[i][j] = 0ull;

    int tx = tid & 15, ty = tid >> 4;
    int am = tid >> 1, ak = (tid & 1) * 4;
    int bk = tid >> 5, bn = (tid & 31) * 4;

    for (int k0 = 0; k0 < 256; k0 += 8) {
        float4 av = *(const float4*)&d_X[(size_t)(m0 + am) * 256 + k0 + ak];
        float4 bv = *(const float4*)&W[(size_t)(k0 + bk) * G4 + n0 + bn];
        As2[(ak + 0) * 128 + am] = pk2(av.x, av.x);
        As2[(ak + 1) * 128 + am] = pk2(av.y, av.y);
        As2[(ak + 2) * 128 + am] = pk2(av.z, av.z);
        As2[(ak + 3) * 128 + am] = pk2(av.w, av.w);
        *(float4*)&Bs[bk * 128 + bn] = bv;
        __syncthreads();
        #pragma unroll
        for (int k = 0; k < 8; k++) {
            ulonglong2 a01 = *(const ulonglong2*)&As2[k * 128 + ty * 8];
            ulonglong2 a23 = *(const ulonglong2*)&As2[k * 128 + ty * 8 + 2];
            ulonglong2 a45 = *(const ulonglong2*)&As2[k * 128 + ty * 8 + 4];
            ulonglong2 a67 = *(const ulonglong2*)&As2[k * 128 + ty * 8 + 6];
            ulonglong2 bq0 = *(const ulonglong2*)&Bs[k * 128 + tx * 8];
            ulonglong2 bq1 = *(const ulonglong2*)&Bs[k * 128 + tx * 8 + 4];
            ull ad[8] = {a01.x, a01.y, a23.x, a23.y, a45.x, a45.y, a67.x, a67.y};
            ull bp[4] = {bq0.x, bq0.y, bq1.x, bq1.y};
            #pragma unroll
            for (int i = 0; i < 8; i++)
                #pragma unroll
                for (int j = 0; j < 4; j++) ffma2(acc[i][j], ad[i], bp[j]);
        }
        __syncthreads();
    }
    #pragma unroll
    for (int i = 0; i < 8; i++) {
        int m = m0 + ty * 8 + i;
        int bIdx = m >> 9;
        int t    = m & 511;
        float* crow = d_ZX + ((size_t)t * BATCH + bIdx) * G4 + n0 + tx * 8;
        const float* brow = bias + n0 + tx * 8;
        #pragma unroll
        for (int j = 0; j < 4; j++) {
            float lo, hi; upk2(acc[i][j], lo, hi);
            crow[j * 2 + 0] = lo + brow[j * 2 + 0];
            crow[j * 2 + 1] = hi + brow[j * 2 + 1];
        }
    }
}

// ---------------- grid barrier (all NCTA_REC CTAs resident: 1 CTA/SM) ----------------
__device__ __forceinline__ void grid_sync() {
    __threadfence();           // every thread: make my stores visible device-wide
    __syncthreads();
    if (threadIdx.x == 0) {
        unsigned gen = *(volatile unsigned*)&g_gen;
        __threadfence();
        if (atomicAdd(&g_cnt, 1u) == NCTA_REC - 1) {
            *(volatile unsigned*)&g_cnt = 0;
            __threadfence();
            atomicAdd(&g_gen, 1u);
        } else {
            while (*(volatile unsigned*)&g_gen == gen) { }
        }
        __threadfence();
    }
    __syncthreads();
}

// ---------------- persistent LSTM: 512 encoder + 64 decoder steps ----------------
// 128 CTAs: ub (16 u-tiles x 16 units) x bb (8 b-tiles x 32 batches), 128 threads.
// thread = (tu unit 0..15, tb 0..7 -> 4 batches). c state lives in registers.
__global__ __launch_bounds__(128, 1) void lstm_persistent(
    const float* __restrict__ encU, const float* __restrict__ cellW,
    const float* __restrict__ cellU, const float* __restrict__ cellB)
{
    extern __shared__ char smem_raw[];
    ull*   Us2 = (ull*)smem_raw;                       // [256][64] dup pairs (128 KB)
    float* hT  = (float*)(smem_raw + 256 * 64 * 8);    // [256][32]            (32 KB)

    int tid = threadIdx.x;
    int tu = tid & 15;
    int tb = tid >> 4;
    int ub = blockIdx.x & 15;
    int bb = blockIdx.x >> 4;
    int u0 = ub * 16;
    int b0 = bb * 32;
    int u  = u0 + tu;

    // encoder U -> smem, duplicated into both f32x2 lanes; col = uu*4 + gate
    for (int idx = tid; idx < 256 * 64; idx += 128) {
        int k = idx >> 6, col = idx & 63;
        int g = col & 3, uu = col >> 2;
        float v = encU[(size_t)k * G4 + g * 256 + u0 + uu];
        Us2[idx] = pk2(v, v);
    }

    float c[4] = {0.f, 0.f, 0.f, 0.f};

    for (int s = 0; s < SEQL + OUTSTEPS; s++) {
        int dec = (s >= SEQL);
        int t = dec ? s - SEQL : s;

        if (s == SEQL) {   // swap weights to decoder (cell_W + cell_U folded)
            __syncthreads();
            for (int idx = tid; idx < 256 * 64; idx += 128) {
                int k = idx >> 6, col = idx & 63;
                int g = col & 3, uu = col >> 2;
                size_t o = (size_t)k * G4 + g * 256 + u0 + uu;
                float v = cellW[o] + cellU[o];
                Us2[idx] = pk2(v, v);
            }
        }

        // ---- stage h_prev into smem (transposed) ----
        if (s == 0) {
            float4 z4 = make_float4(0.f, 0.f, 0.f, 0.f);
            for (int i = tid; i < 2048; i += 128) ((float4*)hT)[i] = z4;
        } else {
            const float* hin = d_Hbuf[s & 1];
            int bl = tid >> 2;
            int k0 = (tid & 3) * 64;
            const float4* src = (const float4*)(hin + (size_t)(b0 + bl) * UNITS + k0);
            #pragma unroll
            for (int j = 0; j < 16; j++) {
                float4 v = __ldcg(src + j);        // bypass L1 (cross-SM producer)
                int k = k0 + j * 4;
                hT[(k + 0) * 32 + bl] = v.x;
                hT[(k + 1) * 32 + bl] = v.y;
                hT[(k + 2) * 32 + bl] = v.z;
                hT[(k + 3) * 32 + bl] = v.w;
            }
        }

        // ---- z init: encoder reads precomputed x@W+b; decoder uses bias ----
        float zini[4][4];
        if (!dec) {
            #pragma unroll
            for (int i2 = 0; i2 < 4; i2++) {
                int b = b0 + tb * 4 + i2;
                const float* r = d_ZX + ((size_t)t * BATCH + b) * G4 + u;
                #pragma unroll
                for (int g = 0; g < 4; g++) zini[i2][g] = __ldcg(r + g * 256);
            }
        } else {
            #pragma unroll
            for (int g = 0; g < 4; g++) {
                float bv = __ldg(cellB + g * 256 + u);
                #pragma unroll
                for (int i2 = 0; i2 < 4; i2++) zini[i2][g] = bv;
            }
        }
        __syncthreads();

        // ---- acc = h @ U  (f32x2, lanes = batch pairs) ----
        ull acc[2][4];
        #pragma unroll
        for (int p = 0; p < 2; p++)
            #pragma unroll
            for (int g = 0; g < 4; g++) acc[p][g] = 0ull;

        const ull* ucol = Us2 + tu * 4;
        const float* hrow = hT + tb * 4;
        #pragma unroll 8
        for (int k = 0; k < 256; k++) {
            ulonglong2 uv01 = *(const ulonglong2*)(ucol + (size_t)k * 64);
            ulonglong2 uv23 = *(const ulonglong2*)(ucol + (size_t)k * 64 + 2);
            ulonglong2 hv   = *(const ulonglong2*)(hrow + (size_t)k * 32);
            ffma2(acc[0][0], hv.x, uv01.x);
            ffma2(acc[0][1], hv.x, uv01.y);
            ffma2(acc[0][2], hv.x, uv23.x);
            ffma2(acc[0][3], hv.x, uv23.y);
            ffma2(acc[1][0], hv.y, uv01.x);
            ffma2(acc[1][1], hv.y, uv01.y);
            ffma2(acc[1][2], hv.y, uv23.x);
            ffma2(acc[1][3], hv.y, uv23.y);
        }

        // ---- gates + state update ----
        float* hout = d_Hbuf[(s + 1) & 1];
        #pragma unroll
        for (int i2 = 0; i2 < 4; i2++) {
            int p = i2 >> 1, lane = i2 & 1;
            float zg4[4];
            #pragma unroll
            for (int g = 0; g < 4; g++) {
                float lo, hi; upk2(acc[p][g], lo, hi);
                zg4[g] = (lane ? hi : lo) + zini[i2][g];
            }
            float ig = 1.f / (1.f + __expf(-zg4[0]));
            float fg = 1.f / (1.f + __expf(-zg4[1]));
            float gg = tanhf(zg4[2]);
            float og = 1.f / (1.f + __expf(-zg4[3]));
            float cn = fg * c[i2] + ig * gg;
            float hn = og * tanhf(cn);
            c[i2] = cn;
            int b = b0 + tb * 4 + i2;
            hout[(size_t)b * UNITS + u] = hn;
            if (!dec) d_HSEQ[((size_t)b * SEQL + t) * UNITS + u] = hn;
            else      d_FSEQ[((size_t)b * OUTSTEPS + t) * UNITS + u] = hn;
        }

        grid_sync();
    }
}

// ---------------- backcast = HSEQ @ back_W + back_b (M=131072, N=64, K=256), f32x2 ----------------
__global__ __launch_bounds__(256) void gemm_back_kernel(
    const float* __restrict__ Bw, const float* __restrict__ bias, float* __restrict__ out)
{
    __shared__ __align__(16) ull   As2[16 * 64];
    __shared__ __align__(16) float Bs [16 * 64];
    int tid = threadIdx.x;
    int m0 = blockIdx.x * 64;
    int tx = tid & 15, ty = tid >> 4;
    ull acc[4][2];
    #pragma unroll
    for (int i = 0; i < 4; i++) { acc[i][0] = 0ull; acc[i][1] = 0ull; }
    int lam = tid >> 2, lak = (tid & 3) * 4;
    int lbk = tid >> 4, lbn = (tid & 15) * 4;
    for (int k0 = 0; k0 < 256; k0 += 16) {
        float4 av = *(const float4*)&d_HSEQ[(size_t)(m0 + lam) * 256 + k0 + lak];
        float4 bv = *(const float4*)&Bw[(size_t)(k0 + lbk) * 64 + lbn];
        As2[(lak + 0) * 64 + lam] = pk2(av.x, av.x);
        As2[(lak + 1) * 64 + lam] = pk2(av.y, av.y);
        As2[(lak + 2) * 64 + lam] = pk2(av.z, av.z);
        As2[(lak + 3) * 64 + lam] = pk2(av.w, av.w);
        *(float4*)&Bs[lbk * 64 + lbn] = bv;
        __syncthreads();
        #pragma unroll
        for (int k = 0; k < 16; k++) {
            ulonglong2 a01 = *(const ulonglong2*)&As2[k * 64 + ty * 4];
            ulonglong2 a23 = *(const ulonglong2*)&As2[k * 64 + ty * 4 + 2];
            ulonglong2 bq  = *(const ulonglong2*)&Bs[k * 64 + tx * 4];
            ffma2(acc[0][0], a01.x, bq.x); ffma2(acc[0][1], a01.x, bq.y);
            ffma2(acc[1][0], a01.y, bq.x); ffma2(acc[1][1], a01.y, bq.y);
            ffma2(acc[2][0], a23.x, bq.x); ffma2(acc[2][1], a23.x, bq.y);
            ffma2(acc[3][0], a23.y, bq.x); ffma2(acc[3][1], a23.y, bq.y);
        }
        __syncthreads();
    }
    #pragma unroll
    for (int i = 0; i < 4; i++) {
        int m = m0 + ty * 4 + i;
        #pragma unroll
        for (int j = 0; j < 2; j++) {
            float lo, hi; upk2(acc[i][j], lo, hi);
            int n = tx * 4 + j * 2;
            out[(size_t)m * 64 + n]     = lo + bias[n];
            out[(size_t)m * 64 + n + 1] = hi + bias[n + 1];
        }
    }
}

// ---------------- forecast = FSEQ @ fore_W + fore_b (M=16384, N=32, K=256) ----------------
__global__ __launch_bounds__(256) void forecast_kernel(
    const float* __restrict__ Wf, const float* __restrict__ bf, float* __restrict__ out)
{
    __shared__ __align__(16) float rows[8][256];
    int tid = threadIdx.x;
    int m0 = blockIdx.x * 8;
    #pragma unroll
    for (int i = 0; i < 8; i++) {
        int flat = tid + 256 * i;
        int r = flat >> 8, cc = flat & 255;
        rows[r][cc] = d_FSEQ[(size_t)(m0 + r) * 256 + cc];
    }
    __syncthreads();
    int r = tid >> 5, n = tid & 31;
    float acc = bf[n];
    #pragma unroll 8
    for (int k = 0; k < 256; k++) acc += rows[r][k] * Wf[k * 32 + n];
    out[(size_t)(m0 + r) * 32 + n] = acc;
}

// ---------------- launch ----------------
extern "C" void kernel_launch(void* const* d_in, const int* in_sizes, int n_in,
                              void* d_out, int out_size)
{
    const float* inputs = (const float*)d_in[0];
    const float* conv_k = (const float*)d_in[1];
    const float* conv_b = (const float*)d_in[2];
    const float* enc_W  = (const float*)d_in[3];
    const float* enc_U  = (const float*)d_in[4];
    const float* enc_b  = (const float*)d_in[5];
    const float* cell_W = (const float*)d_in[6];
    const float* cell_U = (const float*)d_in[7];
    const float* cell_b = (const float*)d_in[8];
    const float* fore_W = (const float*)d_in[9];
    const float* fore_b = (const float*)d_in[10];
    const float* back_W = (const float*)d_in[11];
    const float* back_b = (const float*)d_in[12];
    float* out = (float*)d_out;

    const int rec_smem = 256 * 64 * 8 + 256 * 32 * 4;   // 163840 B
    cudaFuncSetAttribute(lstm_persistent,
                         cudaFuncAttributeMaxDynamicSharedMemorySize, rec_smem);

    conv_relu_kernel<<<dim3(SEQL / 32, BATCH), 256>>>(inputs, conv_k, conv_b);
    gemm_zx_kernel<<<dim3(G4 / 128, (BATCH * SEQL) / 128), 256>>>(enc_W, enc_b);
    lstm_persistent<<<NCTA_REC, 128, rec_smem>>>(enc_U, cell_W, cell_U, cell_b);
    forecast_kernel<<<(BATCH * OUTSTEPS) / 8, 256>>>(fore_W, fore_b, out);
    gemm_back_kernel<<<(BATCH * SEQL) / 64, 256>>>(back_W, back_b,
                                                   out + (size_t)BATCH * OUTSTEPS * OUTDIMS);
}

// round 3
// speedup vs baseline: 1.4835x; 1.3930x over previous
#include <cuda_runtime.h>
#include <cstdint>
#include <math.h>

#define BATCH    256
#define SEQL     512
#define INDIM    64
#define UNITS    256
#define OUTSTEPS 64
#define OUTDIMS  32
#define G4       1024   // 4 * UNITS
#define NCTA_REC 128

typedef unsigned long long ull;

// ---------------- scratch (static device globals; no allocation) ----------------
__device__ float d_X[BATCH * SEQL * UNITS];            // conv output
__device__ float d_ZX[(size_t)SEQL * BATCH * G4];      // x@W + b, [t][b][1024]
__device__ float d_HSEQ[BATCH * SEQL * UNITS];         // encoder hidden seq
__device__ float d_FSEQ[BATCH * OUTSTEPS * UNITS];     // decoder hidden seq
__device__ float d_Hbuf[2][BATCH * UNITS];             // ping-pong h
__device__ unsigned g_cnt = 0;                          // grid barrier
__device__ unsigned g_gen = 0;

// ---------------- f32x2 helpers ----------------
__device__ __forceinline__ ull pk2(float lo, float hi) {
    ull r; asm("mov.b64 %0, {%1, %2};" : "=l"(r) : "f"(lo), "f"(hi)); return r;
}
__device__ __forceinline__ void upk2(ull v, float& lo, float& hi) {
    asm("mov.b64 {%0, %1}, %2;" : "=f"(lo), "=f"(hi) : "l"(v));
}
__device__ __forceinline__ void ffma2(ull& d, ull a, ull b) {
    asm("fma.rn.f32x2 %0, %1, %2, %0;" : "+l"(d) : "l"(a), "l"(b));
}
__device__ __forceinline__ void fadd2(ull& d, ull a) {
    asm("add.rn.f32x2 %0, %0, %1;" : "+l"(d) : "l"(a));
}

// ---------------- conv1d 'same' (K=5) + bias + relu, f32x2 over unit pairs ----------------
__global__ __launch_bounds__(256) void conv_relu_kernel(
    const float* __restrict__ in, const float* __restrict__ ck, const float* __restrict__ cb)
{
    __shared__ __align__(16) ull ins2[36 * 64];
    int tid = threadIdx.x;
    int l0 = blockIdx.x * 32;
    int b  = blockIdx.y;
    for (int idx = tid; idx < 36 * 64; idx += 256) {
        int r = idx >> 6, ci = idx & 63;
        int l = l0 - 2 + r;
        float v = (l >= 0 && l < SEQL) ? in[((size_t)b * SEQL + l) * INDIM + ci] : 0.f;
        ins2[idx] = pk2(v, v);
    }
    __syncthreads();

    int tu = tid & 127;
    int lh = tid >> 7;
    int lbase = lh * 16;
    ull acc[16];
    ull binit = *(const ull*)&cb[2 * tu];
    #pragma unroll
    for (int j = 0; j < 16; j++) acc[j] = binit;

    for (int i = 0; i < 64; i++) {
        ull v2[20];
        #pragma unroll
        for (int r = 0; r < 20; r++) v2[r] = ins2[(lbase + r) * 64 + i];
        #pragma unroll
        for (int w = 0; w < 5; w++) {
            ull kw2 = *(const ull*)&ck[((size_t)(w * 64 + i)) * 256 + 2 * tu];
            #pragma unroll
            for (int j = 0; j < 16; j++) ffma2(acc[j], v2[j + w], kw2);
        }
    }
    #pragma unroll
    for (int j = 0; j < 16; j++) {
        float a, c2; upk2(acc[j], a, c2);
        float2 o = make_float2(fmaxf(a, 0.f), fmaxf(c2, 0.f));
        *(float2*)&d_X[((size_t)b * SEQL + l0 + lbase + j) * UNITS + 2 * tu] = o;
    }
}

// ---------------- ZX = X @ enc_W + enc_b (M=131072, N=1024, K=256), f32x2 ----------------
__global__ __launch_bounds__(256) void gemm_zx_kernel(
    const float* __restrict__ W, const float* __restrict__ bias)
{
    __shared__ __align__(16) ull   As2[8 * 128];
    __shared__ __align__(16) float Bs [8 * 128];
    int tid = threadIdx.x;
    int n0 = blockIdx.x * 128;
    int m0 = blockIdx.y * 128;
    ull acc[8][4];
    #pragma unroll
    for (int i = 0; i < 8; i++)
        #pragma unroll
        for (int j = 0; j < 4; j++) acc[i][j] = 0ull;

    int tx = tid & 15, ty = tid >> 4;
    int am = tid >> 1, ak = (tid & 1) * 4;
    int bk = tid >> 5, bn = (tid & 31) * 4;

    for (int k0 = 0; k0 < 256; k0 += 8) {
        float4 av = *(const float4*)&d_X[(size_t)(m0 + am) * 256 + k0 + ak];
        float4 bv = *(const float4*)&W[(size_t)(k0 + bk) * G4 + n0 + bn];
        As2[(ak + 0) * 128 + am] = pk2(av.x, av.x);
        As2[(ak + 1) * 128 + am] = pk2(av.y, av.y);
        As2[(ak + 2) * 128 + am] = pk2(av.z, av.z);
        As2[(ak + 3) * 128 + am] = pk2(av.w, av.w);
        *(float4*)&Bs[bk * 128 + bn] = bv;
        __syncthreads();
        #pragma unroll
        for (int k = 0; k < 8; k++) {
            ulonglong2 a01 = *(const ulonglong2*)&As2[k * 128 + ty * 8];
            ulonglong2 a23 = *(const ulonglong2*)&As2[k * 128 + ty * 8 + 2];
            ulonglong2 a45 = *(const ulonglong2*)&As2[k * 128 + ty * 8 + 4];
            ulonglong2 a67 = *(const ulonglong2*)&As2[k * 128 + ty * 8 + 6];
            ulonglong2 bq0 = *(const ulonglong2*)&Bs[k * 128 + tx * 8];
            ulonglong2 bq1 = *(const ulonglong2*)&Bs[k * 128 + tx * 8 + 4];
            ull ad[8] = {a01.x, a01.y, a23.x, a23.y, a45.x, a45.y, a67.x, a67.y};
            ull bp[4] = {bq0.x, bq0.y, bq1.x, bq1.y};
            #pragma unroll
            for (int i = 0; i < 8; i++)
                #pragma unroll
                for (int j = 0; j < 4; j++) ffma2(acc[i][j], ad[i], bp[j]);
        }
        __syncthreads();
    }
    #pragma unroll
    for (int i = 0; i < 8; i++) {
        int m = m0 + ty * 8 + i;
        int bIdx = m >> 9;
        int t    = m & 511;
        float* crow = d_ZX + ((size_t)t * BATCH + bIdx) * G4 + n0 + tx * 8;
        const float* brow = bias + n0 + tx * 8;
        #pragma unroll
        for (int j = 0; j < 4; j++) {
            float lo, hi; upk2(acc[i][j], lo, hi);
            crow[j * 2 + 0] = lo + brow[j * 2 + 0];
            crow[j * 2 + 1] = hi + brow[j * 2 + 1];
        }
    }
}

// ---------------- grid barrier ----------------
__device__ __forceinline__ void grid_sync() {
    __threadfence();
    __syncthreads();
    if (threadIdx.x == 0) {
        unsigned gen = *(volatile unsigned*)&g_gen;
        if (atomicAdd(&g_cnt, 1u) == NCTA_REC - 1) {
            *(volatile unsigned*)&g_cnt = 0;
            __threadfence();
            atomicAdd(&g_gen, 1u);
        } else {
            while (*(volatile unsigned*)&g_gen == gen) { }
        }
        __threadfence();
    }
    __syncthreads();
}

// ---------------- persistent LSTM: register-resident U, broadcast-h ----------------
// 128 CTAs x 256 threads. CTA = 16 units (64 gate-cols) x 32 batches, full K=256.
// Compute role: thread (kq = tid>>5 in 0..7 -> k-slice of 32, cp = tid&31 -> col pair).
//   U[32k][1 colpair] in registers (64 regs), h duplicated (h,h) in smem b-major,
//   inner loop: LDS.128 of 2 k's dup-h -> 2 ffma2. Split-k reduced via smem.
// Gate role: thread (guu = tid&15 unit, gbl = tid>>4 batch-within-pass). 2 passes x 16 b.
__global__ __launch_bounds__(256, 1) void lstm_persistent(
    const float* __restrict__ encU, const float* __restrict__ cellW,
    const float* __restrict__ cellU, const float* __restrict__ cellB)
{
    extern __shared__ char smem_raw[];
    ull* hdup = (ull*)smem_raw;                 // [32 b][256 k] dup pairs, 64 KB
    ull* red  = (ull*)(smem_raw + 65536);       // [16 b][8 kq][32 cp], 32 KB

    int tid = threadIdx.x;
    int kq = tid >> 5;          // 0..7
    int cp = tid & 31;          // 0..31
    int ct = blockIdx.x & 15;   // col tile
    int bt = blockIdx.x >> 4;   // batch tile
    int u0 = ct * 16;
    int b0 = bt * 32;
    int uu_c = cp >> 1;
    int gb   = (cp & 1) * 2;    // gate base: 0 -> (i,f), 2 -> (g,o)

    // gate-role indices
    int guu = tid & 15;
    int gbl = tid >> 4;         // 0..15
    int gu  = u0 + guu;

    // ---- load encoder U into registers (once) ----
    ull Ureg[32];
    {
        const float* up = encU + (size_t)(kq * 32) * G4 + gb * 256 + u0 + uu_c;
        #pragma unroll
        for (int k = 0; k < 32; k++)
            Ureg[k] = pk2(__ldg(up + (size_t)k * G4), __ldg(up + (size_t)k * G4 + 256));
    }

    float cst[2] = {0.f, 0.f};
    float bz[4]  = {0.f, 0.f, 0.f, 0.f};

    #pragma unroll 1
    for (int s = 0; s < SEQL + OUTSTEPS; s++) {
        int dec = (s >= SEQL);
        int t = dec ? s - SEQL : s;

        if (s == SEQL) {   // switch to decoder weights: cell_W + cell_U folded
            const float* wp = cellW + (size_t)(kq * 32) * G4 + gb * 256 + u0 + uu_c;
            const float* vp = cellU + (size_t)(kq * 32) * G4 + gb * 256 + u0 + uu_c;
            #pragma unroll
            for (int k = 0; k < 32; k++) {
                size_t o = (size_t)k * G4;
                Ureg[k] = pk2(__ldg(wp + o) + __ldg(vp + o),
                              __ldg(wp + o + 256) + __ldg(vp + o + 256));
            }
            #pragma unroll
            for (int g = 0; g < 4; g++) bz[g] = __ldg(cellB + g * 256 + gu);
        }

        // ---- stage h_prev into smem as dup pairs, b-major ----
        if (s == 0) {
            for (int idx = tid; idx < 32 * 256; idx += 256) hdup[idx] = 0ull;
        } else {
            const float* hin = d_Hbuf[s & 1];
            #pragma unroll
            for (int i = 0; i < 8; i++) {
                int flat = tid + 256 * i;
                int k4 = (flat & 63) * 4;
                int bl = flat >> 6;
                float4 v = __ldcg((const float4*)(hin + (size_t)(b0 + bl) * UNITS + k4));
                ull* dst = hdup + bl * 256 + k4;
                dst[0] = pk2(v.x, v.x); dst[1] = pk2(v.y, v.y);
                dst[2] = pk2(v.z, v.z); dst[3] = pk2(v.w, v.w);
            }
        }

        // ---- prefetch z-init (gate role) while staging settles ----
        float zini[2][4];
        if (!dec) {
            #pragma unroll
            for (int p = 0; p < 2; p++) {
                int b = b0 + p * 16 + gbl;
                const float* r = d_ZX + ((size_t)t * BATCH + b) * G4 + gu;
                #pragma unroll
                for (int g = 0; g < 4; g++) zini[p][g] = __ldcg(r + g * 256);
            }
        } else {
            #pragma unroll
            for (int p = 0; p < 2; p++)
                #pragma unroll
                for (int g = 0; g < 4; g++) zini[p][g] = bz[g];
        }
        __syncthreads();

        float* hout = d_Hbuf[(s + 1) & 1];

        #pragma unroll 1
        for (int p = 0; p < 2; p++) {
            int boff = p * 16;

            // ---- partial z = h @ U over this thread's k-slice ----
            ull acc[16];
            #pragma unroll
            for (int b = 0; b < 16; b++) acc[b] = 0ull;

            #pragma unroll
            for (int kk = 0; kk < 16; kk++) {
                #pragma unroll
                for (int b = 0; b < 16; b++) {
                    ulonglong2 h2 = *(const ulonglong2*)
                        &hdup[(boff + b) * 256 + kq * 32 + kk * 2];
                    ffma2(acc[b], h2.x, Ureg[kk * 2]);
                    ffma2(acc[b], h2.y, Ureg[kk * 2 + 1]);
                }
            }

            // ---- split-k reduction via smem ----
            #pragma unroll
            for (int b = 0; b < 16; b++)
                red[(b * 8 + kq) * 32 + cp] = acc[b];
            __syncthreads();

            // ---- gates (thread = (guu, gbl)) ----
            ull zif = 0ull, zgo = 0ull;
            #pragma unroll
            for (int q = 0; q < 8; q++) {
                ulonglong2 v = *(const ulonglong2*)&red[(gbl * 8 + q) * 32 + 2 * guu];
                fadd2(zif, v.x);
                fadd2(zgo, v.y);
            }
            float zi, zf, zg, zo;
            upk2(zif, zi, zf);
            upk2(zgo, zg, zo);
            zi += zini[p][0]; zf += zini[p][1]; zg += zini[p][2]; zo += zini[p][3];

            float ig = 1.f / (1.f + __expf(-zi));
            float fg = 1.f / (1.f + __expf(-zf));
            float gg = tanhf(zg);
            float og = 1.f / (1.f + __expf(-zo));
            float cn = fg * cst[p] + ig * gg;
            float hn = og * tanhf(cn);
            cst[p] = cn;

            int b = b0 + boff + gbl;
            hout[(size_t)b * UNITS + gu] = hn;
            if (!dec) d_HSEQ[((size_t)b * SEQL + t) * UNITS + gu] = hn;
            else      d_FSEQ[((size_t)b * OUTSTEPS + t) * UNITS + gu] = hn;

            __syncthreads();   // red reused by next pass
        }

        grid_sync();
    }
}

// ---------------- backcast = HSEQ @ back_W + back_b (M=131072, N=64, K=256), f32x2 ----------------
__global__ __launch_bounds__(256) void gemm_back_kernel(
    const float* __restrict__ Bw, const float* __restrict__ bias, float* __restrict__ out)
{
    __shared__ __align__(16) ull   As2[16 * 64];
    __shared__ __align__(16) float Bs [16 * 64];
    int tid = threadIdx.x;
    int m0 = blockIdx.x * 64;
    int tx = tid & 15, ty = tid >> 4;
    ull acc[4][2];
    #pragma unroll
    for (int i = 0; i < 4; i++) { acc[i][0] = 0ull; acc[i][1] = 0ull; }
    int lam = tid >> 2, lak = (tid & 3) * 4;
    int lbk = tid >> 4, lbn = (tid & 15) * 4;
    for (int k0 = 0; k0 < 256; k0 += 16) {
        float4 av = *(const float4*)&d_HSEQ[(size_t)(m0 + lam) * 256 + k0 + lak];
        float4 bv = *(const float4*)&Bw[(size_t)(k0 + lbk) * 64 + lbn];
        As2[(lak + 0) * 64 + lam] = pk2(av.x, av.x);
        As2[(lak + 1) * 64 + lam] = pk2(av.y, av.y);
        As2[(lak + 2) * 64 + lam] = pk2(av.z, av.z);
        As2[(lak + 3) * 64 + lam] = pk2(av.w, av.w);
        *(float4*)&Bs[lbk * 64 + lbn] = bv;
        __syncthreads();
        #pragma unroll
        for (int k = 0; k < 16; k++) {
            ulonglong2 a01 = *(const ulonglong2*)&As2[k * 64 + ty * 4];
            ulonglong2 a23 = *(const ulonglong2*)&As2[k * 64 + ty * 4 + 2];
            ulonglong2 bq  = *(const ulonglong2*)&Bs[k * 64 + tx * 4];
            ffma2(acc[0][0], a01.x, bq.x); ffma2(acc[0][1], a01.x, bq.y);
            ffma2(acc[1][0], a01.y, bq.x); ffma2(acc[1][1], a01.y, bq.y);
            ffma2(acc[2][0], a23.x, bq.x); ffma2(acc[2][1], a23.x, bq.y);
            ffma2(acc[3][0], a23.y, bq.x); ffma2(acc[3][1], a23.y, bq.y);
        }
        __syncthreads();
    }
    #pragma unroll
    for (int i = 0; i < 4; i++) {
        int m = m0 + ty * 4 + i;
        #pragma unroll
        for (int j = 0; j < 2; j++) {
            float lo, hi; upk2(acc[i][j], lo, hi);
            int n = tx * 4 + j * 2;
            out[(size_t)m * 64 + n]     = lo + bias[n];
            out[(size_t)m * 64 + n + 1] = hi + bias[n + 1];
        }
    }
}

// ---------------- forecast = FSEQ @ fore_W + fore_b ----------------
__global__ __launch_bounds__(256) void forecast_kernel(
    const float* __restrict__ Wf, const float* __restrict__ bf, float* __restrict__ out)
{
    __shared__ __align__(16) float rows[8][256];
    int tid = threadIdx.x;
    int m0 = blockIdx.x * 8;
    #pragma unroll
    for (int i = 0; i < 8; i++) {
        int flat = tid + 256 * i;
        int r = flat >> 8, cc = flat & 255;
        rows[r][cc] = d_FSEQ[(size_t)(m0 + r) * 256 + cc];
    }
    __syncthreads();
    int r = tid >> 5, n = tid & 31;
    float acc = bf[n];
    #pragma unroll 8
    for (int k = 0; k < 256; k++) acc += rows[r][k] * Wf[k * 32 + n];
    out[(size_t)(m0 + r) * 32 + n] = acc;
}

// ---------------- launch ----------------
extern "C" void kernel_launch(void* const* d_in, const int* in_sizes, int n_in,
                              void* d_out, int out_size)
{
    const float* inputs = (const float*)d_in[0];
    const float* conv_k = (const float*)d_in[1];
    const float* conv_b = (const float*)d_in[2];
    const float* enc_W  = (const float*)d_in[3];
    const float* enc_U  = (const float*)d_in[4];
    const float* enc_b  = (const float*)d_in[5];
    const float* cell_W = (const float*)d_in[6];
    const float* cell_U = (const float*)d_in[7];
    const float* cell_b = (const float*)d_in[8];
    const float* fore_W = (const float*)d_in[9];
    const float* fore_b = (const float*)d_in[10];
    const float* back_W = (const float*)d_in[11];
    const float* back_b = (const float*)d_in[12];
    float* out = (float*)d_out;

    const int rec_smem = 65536 + 32768;   // hdup + red = 96 KB
    cudaFuncSetAttribute(lstm_persistent,
                         cudaFuncAttributeMaxDynamicSharedMemorySize, rec_smem);

    conv_relu_kernel<<<dim3(SEQL / 32, BATCH), 256>>>(inputs, conv_k, conv_b);
    gemm_zx_kernel<<<dim3(G4 / 128, (BATCH * SEQL) / 128), 256>>>(enc_W, enc_b);
    lstm_persistent<<<NCTA_REC, 256, rec_smem>>>(enc_U, cell_W, cell_U, cell_b);
    forecast_kernel<<<(BATCH * OUTSTEPS) / 8, 256>>>(fore_W, fore_b, out);
    gemm_back_kernel<<<(BATCH * SEQL) / 64, 256>>>(back_W, back_b,
                                                   out + (size_t)BATCH * OUTSTEPS * OUTDIMS);
}